// round 2
// baseline (speedup 1.0000x reference)
#include <cuda_runtime.h>
#include <math.h>

// ----------------------------------------------------------------------------
// margin ranking loss (all i<j pairs) + weighted BCE, B=8192.
// labels in {0,1}:
//   equal-label pairs: contribute m each (closed form from n1)
//   mixed pairs:       relu(m - p_pos + p_neg)  -> n1*n0 scalar ops
// ----------------------------------------------------------------------------

#define KA_T 256
#define K2_T 256
#define MAXB 8192
#define GX   16
#define GY   32
#define TILE_MAX 256            // ceil(MAXB / GY)

// scratch (allocation-free rule: __device__ globals)
__device__ float    g_posL[MAXB];
__device__ float    g_negL[MAXB];
__device__ float    g_pos[MAXB];
__device__ float    g_neg[MAXB];
__device__ double   g_bce[128];
__device__ int      g_cnt[128];
__device__ int      g_n1;
__device__ double   g_mixed;
__device__ unsigned g_doneA = 0;
__device__ unsigned g_done2 = 0;

__device__ __forceinline__ float read_margin(const void* p) {
    if (p == nullptr) return 1.0f;
    int v = *(const int*)p;
    if (v >= -1000000 && v <= 1000000) return (float)v;   // int scalar
    return __int_as_float(v);                             // float bits
}

// ---------------------------------------------------------------------------
// Kernel A (32 blocks x 256): BCE partials + per-block compaction by label.
// The last-finishing block scans the 32 counts, scatters segments into
// contiguous g_pos/g_neg, finalizes BCE -> out[1], resets accumulators.
// ---------------------------------------------------------------------------
__global__ void kA(const float* __restrict__ preds,
                   const float* __restrict__ labels,
                   const float* __restrict__ logits,
                   const float* __restrict__ targets,
                   const float* __restrict__ pw_,
                   int n, float* __restrict__ out)
{
    const int tid = threadIdx.x;
    const int b   = blockIdx.x;
    const int i   = b * KA_T + tid;
    const bool inb = (i < n);

    float p = 0.0f;
    bool flag = false;
    double bce = 0.0;
    if (inb) {
        p = preds[i];
        flag = (labels[i] > 0.5f);
        const float x  = logits[i];
        const float t  = targets[i];
        const float pw = pw_[0];
        const float mv = fmaxf(-x, 0.0f);
        const float lw = 1.0f + (pw - 1.0f) * t;
        bce = (double)((1.0f - t) * x
                       + lw * (logf(expf(-mv) + expf(-x - mv)) + mv));
    }

    // ballot-based block compaction (deterministic, order-preserving)
    const int lane = tid & 31, wid = tid >> 5;
    const unsigned bm = __ballot_sync(0xffffffffu, flag);
    const int lpw = __popc(bm & ((1u << lane) - 1u));
    __shared__ int wcnt[8], wbase[9];
    if (lane == 0) wcnt[wid] = __popc(bm);
    __syncthreads();
    if (tid == 0) {
        int a = 0;
        #pragma unroll
        for (int w = 0; w < 8; w++) { wbase[w] = a; a += wcnt[w]; }
        wbase[8] = a;
    }
    __syncthreads();
    if (inb) {
        const int posLocal = wbase[wid] + lpw;
        if (flag) g_posL[b * KA_T + posLocal]         = p;
        else      g_negL[b * KA_T + (tid - posLocal)] = p;
    }

    // block BCE reduce (fp64)
    __shared__ double sd[KA_T];
    sd[tid] = bce;
    __syncthreads();
    for (int off = KA_T >> 1; off; off >>= 1) {
        if (tid < off) sd[tid] += sd[tid + off];
        __syncthreads();
    }
    if (tid == 0) { g_cnt[b] = wbase[8]; g_bce[b] = sd[0]; }

    // last-block merge
    __threadfence();
    __shared__ int isLast;
    if (tid == 0)
        isLast = (atomicAdd(&g_doneA, 1u) == gridDim.x - 1) ? 1 : 0;
    __syncthreads();
    if (!isLast) return;

    const int nb = gridDim.x;
    __shared__ int base[129];
    if (tid == 0) {
        int a = 0;
        for (int s = 0; s < nb; s++) { base[s] = a; a += *(volatile int*)&g_cnt[s]; }
        base[nb] = a;
    }
    __syncthreads();

    // scatter local segments to contiguous arrays (coalesced-ish, .cg loads)
    for (int e = tid; e < n; e += KA_T) {
        const int s = e >> 8;          // KA_T == 256
        const int j = e & 255;
        const int segStart = s * KA_T;
        const int chunkLen = min(KA_T, n - segStart);
        const int c = base[s + 1] - base[s];
        if (j < c)
            g_pos[base[s] + j] = __ldcg(&g_posL[e]);
        if (j < chunkLen - c)
            g_neg[segStart - base[s] + j] = __ldcg(&g_negL[e]);
    }

    if (tid == 0) {
        double sb = 0.0;
        for (int s = 0; s < nb; s++) sb += *(volatile double*)&g_bce[s];
        out[1] = (float)(sb / (double)n);
        g_n1    = base[nb];
        g_mixed = 0.0;
        g_done2 = 0u;
        g_doneA = 0u;          // reset for next graph replay
    }
}

// ---------------------------------------------------------------------------
// Kernel 2 (GX x GY blocks x 256): mixed-pair sum.
//   blockIdx.y: 1/GY slice of neg array, cached once in smem (<=256 floats,
//               stored pre-added with margin, padded with -1e30).
//   blockIdx.x: grid-stride over pos; 1 pos value per thread in a register.
//   Inner loop: float4 smem loads + 4 independent fp32 accumulators (ILP=4).
// ---------------------------------------------------------------------------
__global__ void k2(int n, const void* __restrict__ marginp,
                   float* __restrict__ out)
{
    const int tid = threadIdx.x;
    const float m = read_margin(marginp);
    const int n1 = g_n1;
    const int n0 = n - n1;

    const int nchunk = (n0 + GY - 1) / GY;
    const int ns = blockIdx.y * nchunk;
    const int ne = min(ns + nchunk, n0);
    const int cnt  = max(ne - ns, 0);
    const int cnt4 = (cnt + 3) & ~3;

    __shared__ __align__(16) float tile[TILE_MAX + 4];
    for (int i = tid; i < cnt4; i += K2_T)
        tile[i] = (i < cnt) ? (m + g_neg[ns + i]) : -1e30f;
    __syncthreads();

    double accd = 0.0;
    for (int pb = blockIdx.x * K2_T; pb < n1; pb += GX * K2_T) {
        const int pidx = pb + tid;
        if (pidx < n1) {
            const float a = g_pos[pidx];
            float a0 = 0.f, a1 = 0.f, a2 = 0.f, a3 = 0.f;
            for (int i = 0; i < cnt4; i += 4) {
                const float4 t = *(const float4*)&tile[i];
                a0 += fmaxf(t.x - a, 0.0f);
                a1 += fmaxf(t.y - a, 0.0f);
                a2 += fmaxf(t.z - a, 0.0f);
                a3 += fmaxf(t.w - a, 0.0f);
            }
            accd += (double)((a0 + a1) + (a2 + a3));
        }
    }

    __shared__ double red[K2_T];
    red[tid] = accd;
    __syncthreads();
    for (int off = K2_T >> 1; off; off >>= 1) {
        if (tid < off) red[tid] += red[tid + off];
        __syncthreads();
    }
    if (tid == 0) {
        atomicAdd(&g_mixed, red[0]);
        __threadfence();
        const unsigned prev = atomicAdd(&g_done2, 1u);
        if (prev == (unsigned)(GX * GY) - 1u) {
            const double dn1 = (double)n1, dn0 = (double)n0;
            const double eqPairs = 0.5 * (dn1 * (dn1 - 1.0) + dn0 * (dn0 - 1.0));
            const double eqContrib = (m > 0.0f) ? (double)m * eqPairs : 0.0;
            out[0] = (float)((eqContrib + g_mixed) / (double)n);
        }
    }
}

// ---------------------------------------------------------------------------
extern "C" void kernel_launch(void* const* d_in, const int* in_sizes, int n_in,
                              void* d_out, int out_size)
{
    const float* preds   = (const float*)d_in[0];
    const float* labels  = (const float*)d_in[1];
    const float* logits  = (const float*)d_in[2];
    const float* targets = (const float*)d_in[3];
    const float* pw      = (const float*)d_in[4];
    const void*  marginp = (n_in >= 6) ? d_in[5] : nullptr;
    const int n = in_sizes[0];
    float* out = (float*)d_out;

    kA<<<(n + KA_T - 1) / KA_T, KA_T>>>(preds, labels, logits, targets, pw, n, out);
    k2<<<dim3(GX, GY), K2_T>>>(n, marginp, out);
}

// round 3
// speedup vs baseline: 2.1047x; 2.1047x over previous
#include <cuda_runtime.h>
#include <math.h>

// ----------------------------------------------------------------------------
// margin ranking loss (all i<j pairs) + weighted BCE, B=8192, labels in {0,1}.
//   equal-label pairs: prod=0 -> contribute relu(m) each (closed form from n1)
//   mixed pairs:       relu(m - p_pos + p_neg)        (n1*n0 scalar relu-adds)
// out[0] = (relu(m)*eqPairs + sum_mixed)/B ; out[1] = mean weighted BCE
// ----------------------------------------------------------------------------

#define KA_T 256
#define K2_T 256
#define MAXB 8192
#define GX   4          // pos-side x blocks (cover 4*1024 pos per sweep)
#define GY   64         // neg-side slices
#define REG  4          // pos values per thread, in registers
#define TILE_MAX 144    // >= ceil(MAXB/GY)+pad

// scratch (allocation-free rule: __device__ globals)
__device__ float    g_pos[MAXB];
__device__ float    g_neg[MAXB];
__device__ int      g_posCnt = 0;
__device__ int      g_negCnt = 0;
__device__ double   g_bceSum = 0.0;
__device__ double   g_mixed  = 0.0;
__device__ unsigned g_done2  = 0;

__device__ __forceinline__ float read_margin(const void* p) {
    if (p == nullptr) return 1.0f;
    int v = *(const int*)p;
    if (v >= -1000000 && v <= 1000000) return (float)v;   // int scalar
    return __int_as_float(v);                             // float bits
}

// ---------------------------------------------------------------------------
// Kernel A: 32 blocks x 256, NO block barriers.
//  - per-thread BCE term -> warp shfl reduce -> fp64 atomicAdd
//  - warp ballot compaction + per-warp atomic segment reservation -> scatter
// ---------------------------------------------------------------------------
__global__ void __launch_bounds__(KA_T)
kA(const float* __restrict__ preds,
   const float* __restrict__ labels,
   const float* __restrict__ logits,
   const float* __restrict__ targets,
   const float* __restrict__ pw_,
   int n)
{
    const int tid  = threadIdx.x;
    const int i    = blockIdx.x * KA_T + tid;
    const int lane = tid & 31;
    const bool inb = (i < n);

    float p = 0.0f, bce = 0.0f;
    bool flag = false;
    if (inb) {
        p    = preds[i];
        flag = (labels[i] > 0.5f);
        const float x  = logits[i];
        const float t  = targets[i];
        const float pw = pw_[0];
        const float mv = fmaxf(-x, 0.0f);
        const float sp = __logf(__expf(-mv) + __expf(-x - mv)) + mv;  // softplus(-x)
        bce = (1.0f - t) * x + (1.0f + (pw - 1.0f) * t) * sp;
    }

    // warp BCE reduce
    float w = bce;
    #pragma unroll
    for (int off = 16; off; off >>= 1)
        w += __shfl_down_sync(0xffffffffu, w, off);
    if (lane == 0) atomicAdd(&g_bceSum, (double)w);

    // warp compaction + reservation (order across warps nondeterministic;
    // final sums are commutative reductions, jitter ~1e-9 rel << 1e-3 tol)
    const unsigned bm   = __ballot_sync(0xffffffffu, flag && inb);
    const unsigned vm   = __ballot_sync(0xffffffffu, inb);
    const int      rank = __popc(bm & ((1u << lane) - 1u));
    const int      c    = __popc(bm);
    const int      v    = __popc(vm);
    int bp = 0, bn = 0;
    if (lane == 0) {
        bp = atomicAdd(&g_posCnt, c);
        bn = atomicAdd(&g_negCnt, v - c);
    }
    bp = __shfl_sync(0xffffffffu, bp, 0);
    bn = __shfl_sync(0xffffffffu, bn, 0);
    if (inb) {
        if (flag) g_pos[bp + rank] = p;
        else      g_neg[bn + (__popc(vm & ((1u << lane) - 1u)) - rank)] = p;
    }
}

// ---------------------------------------------------------------------------
// Kernel 2: GX x GY blocks x 256.
//  y: 1/GY slice of neg, cached in smem pre-added with margin (poison -1e30).
//  x: REG=4 pos per thread in registers (poison +1e30), grid-stride if n1>4096.
//  Inner: float4 smem loads, 4 independent fp32 accumulator chains.
//  Last block: finalize out[0], out[1], reset all accumulators.
// ---------------------------------------------------------------------------
__global__ void __launch_bounds__(K2_T)
k2(int n, const void* __restrict__ marginp, float* __restrict__ out)
{
    const int tid = threadIdx.x;
    const float m = read_margin(marginp);
    const int n1 = g_posCnt;
    const int n0 = n - n1;

    // neg slice -> smem
    const int nchunk = (n0 + GY - 1) / GY;
    const int ns   = blockIdx.y * nchunk;
    const int cnt  = max(min(ns + nchunk, n0) - ns, 0);
    const int cnt4 = (cnt + 3) & ~3;

    __shared__ __align__(16) float tile[TILE_MAX];
    for (int i = tid; i < cnt4; i += K2_T)
        tile[i] = (i < cnt) ? (m + g_neg[ns + i]) : -1e30f;
    __syncthreads();

    double accd = 0.0;
    {
        float s0 = 0.f, s1 = 0.f, s2 = 0.f, s3 = 0.f;
        for (int pb = blockIdx.x * (K2_T * REG); pb < n1; pb += GX * K2_T * REG) {
            const int i0 = pb + tid;
            const float a0 = (i0             < n1) ? g_pos[i0]             : 1e30f;
            const float a1 = (i0 + K2_T     < n1) ? g_pos[i0 + K2_T]      : 1e30f;
            const float a2 = (i0 + 2 * K2_T < n1) ? g_pos[i0 + 2 * K2_T]  : 1e30f;
            const float a3 = (i0 + 3 * K2_T < n1) ? g_pos[i0 + 3 * K2_T]  : 1e30f;
            for (int i = 0; i < cnt4; i += 4) {
                const float4 t = *(const float4*)&tile[i];
                s0 += fmaxf(t.x - a0, 0.f); s1 += fmaxf(t.x - a1, 0.f);
                s2 += fmaxf(t.x - a2, 0.f); s3 += fmaxf(t.x - a3, 0.f);
                s0 += fmaxf(t.y - a0, 0.f); s1 += fmaxf(t.y - a1, 0.f);
                s2 += fmaxf(t.y - a2, 0.f); s3 += fmaxf(t.y - a3, 0.f);
                s0 += fmaxf(t.z - a0, 0.f); s1 += fmaxf(t.z - a1, 0.f);
                s2 += fmaxf(t.z - a2, 0.f); s3 += fmaxf(t.z - a3, 0.f);
                s0 += fmaxf(t.w - a0, 0.f); s1 += fmaxf(t.w - a1, 0.f);
                s2 += fmaxf(t.w - a2, 0.f); s3 += fmaxf(t.w - a3, 0.f);
            }
        }
        accd = (double)((s0 + s1) + (s2 + s3));
    }

    // block reduce (warp shfl fp64, then 8 partials)
    const int lane = tid & 31, wid = tid >> 5;
    #pragma unroll
    for (int off = 16; off; off >>= 1)
        accd += __shfl_down_sync(0xffffffffu, accd, off);
    __shared__ double wsum[8];
    if (lane == 0) wsum[wid] = accd;
    __syncthreads();
    if (tid == 0) {
        double b = 0.0;
        #pragma unroll
        for (int w2 = 0; w2 < 8; w2++) b += wsum[w2];
        atomicAdd(&g_mixed, b);
        __threadfence();
        const unsigned prev = atomicAdd(&g_done2, 1u);
        if (prev == (unsigned)(GX * GY) - 1u) {
            const double dn1 = (double)n1, dn0 = (double)n0;
            const double eqPairs = 0.5 * (dn1 * (dn1 - 1.0) + dn0 * (dn0 - 1.0));
            const double mm = (double)fmaxf(m, 0.0f);
            out[0] = (float)((mm * eqPairs + g_mixed) / (double)n);
            out[1] = (float)(g_bceSum / (double)n);
            // reset for next graph replay
            g_posCnt = 0; g_negCnt = 0;
            g_bceSum = 0.0; g_mixed = 0.0; g_done2 = 0u;
        }
    }
}

// ---------------------------------------------------------------------------
extern "C" void kernel_launch(void* const* d_in, const int* in_sizes, int n_in,
                              void* d_out, int out_size)
{
    const float* preds   = (const float*)d_in[0];
    const float* labels  = (const float*)d_in[1];
    const float* logits  = (const float*)d_in[2];
    const float* targets = (const float*)d_in[3];
    const float* pw      = (const float*)d_in[4];
    const void*  marginp = (n_in >= 6) ? d_in[5] : nullptr;
    const int n = in_sizes[0];
    float* out = (float*)d_out;

    kA<<<(n + KA_T - 1) / KA_T, KA_T>>>(preds, labels, logits, targets, pw, n);
    k2<<<dim3(GX, GY), K2_T>>>(n, marginp, out);
}